// round 12
// baseline (speedup 1.0000x reference)
#include <cuda_runtime.h>
#include <cuda_bf16.h>
#include <cstdint>

#define Dh   1024
#define Bn   8
#define Tn   256
#define Vn   32000
#define Rn   2048   // Bn*Tn

// ---------------- scratch (static device allocations; no cudaMalloc) ----------------
__device__ float          g_Wx[Rn * Dh];          // 8 MB
__device__ __nv_bfloat16  g_hbf[Rn * Dh];         // 4 MB
__device__ __nv_bfloat16  g_xbf[Rn * Dh];         // 4 MB
__device__ __nv_bfloat16  g_Wbf[Dh * Dh];         // 2 MB
__device__ __nv_bfloat16  g_Woutbf[Vn * Dh];      // 64 MB
__device__ float          g_rowsum[Rn];           // fused exp-sum per output row
__device__ float          g_part2[2][4][Bn][Dh];  // double-buffered k-split partials
__device__ unsigned int   g_syncc[8 * 32];        // 8 striped arrival counters (128B apart)
__device__ unsigned int   g_master[32];           // second-level counter (own line)
__device__ unsigned int   g_gen[32];              // published generation (own line)

// ---------------- cvt: W + Wout fp32->bf16, zero counters/rowsum ----------------
#define CVT_BLOCKS 2304
__global__ __launch_bounds__(256) void cvt_kernel(const float* __restrict__ W,
                                                  const float* __restrict__ Wout) {
    if (blockIdx.x == 0) {
        if (threadIdx.x < 8) g_syncc[threadIdx.x * 32] = 0u;
        if (threadIdx.x == 8) g_master[0] = 0u;
        if (threadIdx.x == 9) g_gen[0] = 0u;
        for (int i = threadIdx.x; i < Rn; i += 256) g_rowsum[i] = 0.0f;
    }
    const int nW    = Dh * Dh / 4;
    const int nWout = Vn * Dh / 4;
    int i = blockIdx.x * 256 + threadIdx.x;
    const int stride = CVT_BLOCKS * 256;
    for (; i < nW + nWout; i += stride) {
        float4 v;
        __nv_bfloat162* dst;
        if (i < nW) {
            v = ((const float4*)W)[i];
            dst = (__nv_bfloat162*)g_Wbf + 2 * (size_t)i;
        } else {
            int j = i - nW;
            v = ((const float4*)Wout)[j];
            dst = (__nv_bfloat162*)g_Woutbf + 2 * (size_t)j;
        }
        dst[0] = __floats2bfloat162_rn(v.x, v.y);
        dst[1] = __floats2bfloat162_rn(v.z, v.w);
    }
}

// ---------------- embedding gather -> bf16 ----------------
__global__ __launch_bounds__(256) void embed_kernel(const int* __restrict__ idx,
                                                    const float* __restrict__ E) {
    int r = blockIdx.x;
    int id = idx[r];
    const float4* src = (const float4*)(E + (size_t)id * Dh);
    __nv_bfloat162* out = (__nv_bfloat162*)(g_xbf + (size_t)r * Dh);
    for (int i = threadIdx.x; i < Dh / 4; i += 256) {
        float4 v = src[i];
        out[2*i]   = __floats2bfloat162_rn(v.x, v.y);
        out[2*i+1] = __floats2bfloat162_rn(v.z, v.w);
    }
}

// ================= raw mma.sync bf16 NT GEMM: C[m,n] = sum_k A[m,k]*B[n,k] =================
#define BM 128
#define BN 128
#define BK 64
#define NST 3
#define AST (BM * BK * 2)
#define BST (BN * BK * 2)
#define GEMM_DSMEM (NST * (AST + BST))   // 96 KB

__device__ __forceinline__ uint32_t smem_u32(const void* p) {
    uint32_t a;
    asm("{ .reg .u64 t; cvta.to.shared.u64 t, %1; cvt.u32.u64 %0, t; }" : "=r"(a) : "l"(p));
    return a;
}
__device__ __forceinline__ void cp_async16(uint32_t dst, const void* src) {
    asm volatile("cp.async.cg.shared.global [%0], [%1], 16;" :: "r"(dst), "l"(src));
}
__device__ __forceinline__ void cp_commit() { asm volatile("cp.async.commit_group;"); }

__device__ __forceinline__ void ldsm4(uint32_t& r0, uint32_t& r1, uint32_t& r2, uint32_t& r3, uint32_t a) {
    asm volatile("ldmatrix.sync.aligned.m8n8.x4.shared.b16 {%0,%1,%2,%3}, [%4];"
                 : "=r"(r0), "=r"(r1), "=r"(r2), "=r"(r3) : "r"(a));
}
__device__ __forceinline__ void mma16816(float* d, const uint32_t* a, const uint32_t* b) {
    asm volatile("mma.sync.aligned.m16n8k16.row.col.f32.bf16.bf16.f32 "
                 "{%0,%1,%2,%3}, {%4,%5,%6,%7}, {%8,%9}, {%0,%1,%2,%3};"
                 : "+f"(d[0]), "+f"(d[1]), "+f"(d[2]), "+f"(d[3])
                 : "r"(a[0]), "r"(a[1]), "r"(a[2]), "r"(a[3]), "r"(b[0]), "r"(b[1]));
}

template <bool FUSE>
__global__ __launch_bounds__(256, 2) void gemm_mma(const __nv_bfloat16* __restrict__ A,
                                                   const __nv_bfloat16* __restrict__ Bm,
                                                   float* __restrict__ C,
                                                   int Nr, int Kr,
                                                   const float* __restrict__ bias,
                                                   float* __restrict__ rowsum) {
    extern __shared__ char smem[];
    const uint32_t sBase = smem_u32(smem);
    const uint32_t aS = sBase;
    const uint32_t bS = sBase + NST * AST;

    const int tid  = threadIdx.x;
    const int lane = tid & 31;
    const int wid  = tid >> 5;
    const int wm   = wid >> 2;
    const int wn   = wid & 3;
    const int bm = blockIdx.x, bn = blockIdx.y;
    const int KTILES = Kr / BK;

    uint32_t ld_phys[4];
    const __nv_bfloat16* aSrc[4];
    const __nv_bfloat16* bSrc[4];
    #pragma unroll
    for (int q = 0; q < 4; q++) {
        int task = q * 256 + tid;
        int row = task >> 3, ch = task & 7;
        uint32_t col = (uint32_t)ch * 16;
        ld_phys[q] = (uint32_t)row * 128 + (col ^ ((uint32_t)(row & 7) << 4));
        aSrc[q] = A  + (size_t)(bm * BM + row) * Kr + ch * 8;
        bSrc[q] = Bm + (size_t)(bn * BN + row) * Kr + ch * 8;
    }

    uint32_t aRowTerm[4], aPhase[4];
    const uint32_t aChunk = (uint32_t)(lane >> 4) * 16;
    #pragma unroll
    for (int i = 0; i < 4; i++) {
        int r = wm * 64 + i * 16 + (lane & 15);
        aRowTerm[i] = (uint32_t)r * 128;
        aPhase[i]   = (uint32_t)(r & 7) << 4;
    }
    uint32_t bRowTerm[2], bPhase[2];
    const uint32_t bChunk = (uint32_t)((lane >> 3) & 1) * 16;
    #pragma unroll
    for (int j = 0; j < 2; j++) {
        int n = wn * 32 + j * 16 + (lane & 7) + ((lane >> 4) << 3);
        bRowTerm[j] = (uint32_t)n * 128;
        bPhase[j]   = (uint32_t)(n & 7) << 4;
    }

    auto load_stage = [&](int st, int kt) {
        const int k0 = kt * BK;
        const uint32_t aOff = aS + st * AST;
        const uint32_t bOff = bS + st * BST;
        #pragma unroll
        for (int q = 0; q < 4; q++) {
            cp_async16(aOff + ld_phys[q], aSrc[q] + k0);
            cp_async16(bOff + ld_phys[q], bSrc[q] + k0);
        }
    };

    float acc[4][4][4];
    #pragma unroll
    for (int i = 0; i < 4; i++)
        #pragma unroll
        for (int j = 0; j < 4; j++)
            #pragma unroll
            for (int e = 0; e < 4; e++) acc[i][j][e] = 0.0f;

    load_stage(0, 0); cp_commit();
    load_stage(1, 1); cp_commit();

    for (int kt = 0; kt < KTILES; kt++) {
        const int st = kt % NST;
        asm volatile("cp.async.wait_group 1;" ::: "memory");
        __syncthreads();

        const int nf = kt + 2;
        if (nf < KTILES) load_stage(nf % NST, nf);
        cp_commit();

        const uint32_t aStage = aS + st * AST;
        const uint32_t bStage = bS + st * BST;
        #pragma unroll
        for (int s = 0; s < BK / 16; s++) {
            const uint32_t colA = (uint32_t)s * 32 + aChunk;
            const uint32_t colB = (uint32_t)s * 32 + bChunk;
            uint32_t a[4][4];
            #pragma unroll
            for (int i = 0; i < 4; i++)
                ldsm4(a[i][0], a[i][1], a[i][2], a[i][3],
                      aStage + aRowTerm[i] + (colA ^ aPhase[i]));
            uint32_t b[4][2];
            #pragma unroll
            for (int j = 0; j < 2; j++) {
                uint32_t r0, r1, r2, r3;
                ldsm4(r0, r1, r2, r3, bStage + bRowTerm[j] + (colB ^ bPhase[j]));
                b[2*j][0] = r0; b[2*j][1] = r1;
                b[2*j+1][0] = r2; b[2*j+1][1] = r3;
            }
            #pragma unroll
            for (int i = 0; i < 4; i++)
                #pragma unroll
                for (int j = 0; j < 4; j++)
                    mma16816(acc[i][j], a[i], b[j]);
        }
    }

    // ---- epilogue ----
    const int g = lane >> 2, tg = lane & 3;
    #pragma unroll
    for (int i = 0; i < 4; i++) {
        int row0 = bm * BM + wm * 64 + i * 16 + g;
        float p0 = 0.0f, p8 = 0.0f;
        #pragma unroll
        for (int j = 0; j < 4; j++) {
            int col = bn * BN + wn * 32 + j * 8 + tg * 2;
            float b0 = 0.0f, b1 = 0.0f;
            if (FUSE) { b0 = bias[col]; b1 = bias[col + 1]; }
            float v00 = acc[i][j][0] + b0, v01 = acc[i][j][1] + b1;
            float v10 = acc[i][j][2] + b0, v11 = acc[i][j][3] + b1;
            *(float2*)(C + (size_t)row0 * Nr + col)       = make_float2(v00, v01);
            *(float2*)(C + (size_t)(row0 + 8) * Nr + col) = make_float2(v10, v11);
            if (FUSE) {
                p0 += __expf(v00) + __expf(v01);
                p8 += __expf(v10) + __expf(v11);
            }
        }
        if (FUSE) {
            p0 += __shfl_xor_sync(0xffffffffu, p0, 1);
            p0 += __shfl_xor_sync(0xffffffffu, p0, 2);
            p8 += __shfl_xor_sync(0xffffffffu, p8, 1);
            p8 += __shfl_xor_sync(0xffffffffu, p8, 2);
            if (tg == 0) {
                atomicAdd(&rowsum[row0], p0);
                atomicAdd(&rowsum[row0 + 8], p8);
            }
        }
    }
}

// ====== persistent recurrence v4d: R10 compute + last-arriver generation barrier ======
__global__ __launch_bounds__(256) void rnn_kernel(const float* __restrict__ Ug,
                                                  const float* __restrict__ bWv,
                                                  const float* __restrict__ bUv) {
    const int tid  = threadIdx.x;
    const int w    = tid >> 5;
    const int lane = tid & 31;
    const int bi   = blockIdx.x;
    const int eg   = bi >> 2;               // 0..31
    const int kq   = bi & 3;                // 0..3
    const int e    = eg * 32 + lane;        // output e this thread accumulates (phase A)
    const int k0   = kq * 256 + w * 32;     // global k start for this thread's U chunk

    float Ur[32];
    #pragma unroll
    for (int j = 0; j < 32; j++) Ur[j] = Ug[(size_t)e * Dh + k0 + j];

    const int ec = kq * 256 + tid;          // e this thread computes h for (phase C)
    const float bsum = bWv[ec] + bUv[ec];

    __shared__ float sh[8 * 256];           // h[b][k_local]
    __shared__ float sp[8 * 256];           // reduction buffer

    for (int t = 0; t < Tn; t++) {
        // ---- phase A: partial = U[e][k-chunk] . h_{t-1}[b][k-chunk] ----
        float acc[8];
        #pragma unroll
        for (int b = 0; b < 8; b++) acc[b] = 0.0f;
        if (t > 0) {
            #pragma unroll
            for (int b = 0; b < 8; b++) {
                const float4* hp = (const float4*)&sh[b * 256 + w * 32];  // warp-uniform broadcast
                #pragma unroll
                for (int jj = 0; jj < 8; jj++) {
                    float4 h4 = hp[jj];
                    acc[b] = fmaf(Ur[4*jj+0], h4.x, acc[b]);
                    acc[b] = fmaf(Ur[4*jj+1], h4.y, acc[b]);
                    acc[b] = fmaf(Ur[4*jj+2], h4.z, acc[b]);
                    acc[b] = fmaf(Ur[4*jj+3], h4.w, acc[b]);
                }
            }
        }
        #pragma unroll
        for (int b = 0; b < 8; b++) sp[w * 256 + b * 32 + lane] = acc[b];

        // prefetch Wx for phase C (independent of the barrier)
        float wx[8];
        #pragma unroll
        for (int b = 0; b < 8; b++)
            wx[b] = __ldcg(&g_Wx[(size_t)(b * Tn + t) * Dh + ec]);

        __syncthreads();
        {
            float s = sp[tid] + sp[256 + tid] + sp[512 + tid] + sp[768 + tid]
                    + sp[1024 + tid] + sp[1280 + tid] + sp[1536 + tid] + sp[1792 + tid];
            g_part2[t & 1][kq][tid >> 5][eg * 32 + (tid & 31)] = s;
        }
        __syncthreads();

        // ---- two-level last-arriver barrier: polls only touch g_gen's line ----
        if (tid == 0) {
            __threadfence();
            unsigned int r1 = atomicAdd(&g_syncc[(bi & 7) * 32], 1u);
            if (r1 == 16u * (unsigned)(t + 1) - 1u) {
                unsigned int r2 = atomicAdd(&g_master[0], 1u);
                if (r2 == 8u * (unsigned)(t + 1) - 1u) {
                    __threadfence();
                    g_gen[0] = (unsigned)(t + 1);
                }
            }
            while (*(volatile unsigned int*)&g_gen[0] < (unsigned)(t + 1)) { }
        }
        __syncthreads();

        // ---- phase C: recompute h_t for this block's k-range from shared partials ----
        #pragma unroll
        for (int b = 0; b < 8; b++) {
            float s2 = wx[b] + bsum;
            s2 += __ldcg(&g_part2[t & 1][0][b][ec]);
            s2 += __ldcg(&g_part2[t & 1][1][b][ec]);
            s2 += __ldcg(&g_part2[t & 1][2][b][ec]);
            s2 += __ldcg(&g_part2[t & 1][3][b][ec]);
            float h = tanhf(s2);
            sh[b * 256 + tid] = h;
            if (eg == 0)
                g_hbf[(size_t)(b * Tn + t) * Dh + ec] = __float2bfloat16(h);
        }
        __syncthreads();
    }
}

// ---------------- final log_softmax subtract (single vectorized pass) ----------------
__global__ __launch_bounds__(256) void lse_final_kernel(float* __restrict__ C) {
    const int r = blockIdx.x;
    float4* row = (float4*)(C + (size_t)r * Vn);
    const float lse = __logf(g_rowsum[r]);
    for (int i = threadIdx.x; i < Vn / 4; i += 256) {
        float4 v = row[i];
        v.x -= lse; v.y -= lse; v.z -= lse; v.w -= lse;
        row[i] = v;
    }
}

// ---------------- launch ----------------
extern "C" void kernel_launch(void* const* d_in, const int* in_sizes, int n_in,
                              void* d_out, int out_size) {
    const int*   idx  = (const int*)d_in[0];
    const float* E    = (const float*)d_in[1];
    const float* W    = (const float*)d_in[2];
    const float* bW   = (const float*)d_in[3];
    const float* U    = (const float*)d_in[4];
    const float* bU   = (const float*)d_in[5];
    const float* Wout = (const float*)d_in[6];
    const float* bout = (const float*)d_in[7];
    float* out = (float*)d_out;

    void *p_xbf, *p_Wbf, *p_Woutbf, *p_Wx, *p_hbf, *p_rowsum;
    cudaGetSymbolAddress(&p_xbf,    g_xbf);
    cudaGetSymbolAddress(&p_Wbf,    g_Wbf);
    cudaGetSymbolAddress(&p_Woutbf, g_Woutbf);
    cudaGetSymbolAddress(&p_Wx,     g_Wx);
    cudaGetSymbolAddress(&p_hbf,    g_hbf);
    cudaGetSymbolAddress(&p_rowsum, g_rowsum);

    static int attr_set = 0;
    if (!attr_set) {
        cudaFuncSetAttribute(gemm_mma<false>, cudaFuncAttributeMaxDynamicSharedMemorySize, GEMM_DSMEM);
        cudaFuncSetAttribute(gemm_mma<true>,  cudaFuncAttributeMaxDynamicSharedMemorySize, GEMM_DSMEM);
        attr_set = 1;
    }

    // 1) cvt W/Wout + zero counters/rowsum
    cvt_kernel<<<CVT_BLOCKS, 256>>>(W, Wout);

    // 2) embedding gather
    embed_kernel<<<Rn, 256>>>(idx, E);

    // 3) input projection: Wx[r,e] = sum_d x[r,d] * W[e,d]
    gemm_mma<false><<<dim3(Rn / BM, Dh / BN), 256, GEMM_DSMEM>>>(
        (const __nv_bfloat16*)p_xbf, (const __nv_bfloat16*)p_Wbf, (float*)p_Wx,
        Dh, Dh, nullptr, nullptr);

    // 4) recurrence
    rnn_kernel<<<128, 256>>>(U, bW, bU);

    // 5) output projection with fused bias + exp-sum epilogue
    gemm_mma<true><<<dim3(Rn / BM, Vn / BN), 256, GEMM_DSMEM>>>(
        (const __nv_bfloat16*)p_hbf, (const __nv_bfloat16*)p_Woutbf, out,
        Vn, Dh, bout, (float*)p_rowsum);

    // 6) final: subtract log(sum exp) per row
    lse_final_kernel<<<Rn, 256>>>(out);
}

// round 13
// speedup vs baseline: 1.6128x; 1.6128x over previous
#include <cuda_runtime.h>
#include <cuda_bf16.h>
#include <cstdint>

#define Dh   1024
#define Bn   8
#define Tn   256
#define Vn   32000
#define Rn   2048   // Bn*Tn

// ---------------- scratch (static device allocations; no cudaMalloc) ----------------
__device__ float          g_Wx[Rn * Dh];          // 8 MB
__device__ __nv_bfloat16  g_hbf[Rn * Dh];         // 4 MB  (h for final GEMM)
__device__ __nv_bfloat16  g_hcur[2][Bn * Dh];     // double-buffered current h (bf16)
__device__ __nv_bfloat16  g_xbf[Rn * Dh];         // 4 MB
__device__ __nv_bfloat16  g_Wbf[Dh * Dh];         // 2 MB
__device__ __nv_bfloat16  g_Ubf[Dh * Dh];         // 2 MB  (U in bf16 for mma)
__device__ __nv_bfloat16  g_Woutbf[Vn * Dh];      // 64 MB
__device__ float          g_rowsum[Rn];           // fused exp-sum per output row
__device__ volatile unsigned int g_slot[64 * 32]; // padded per-block epoch slots (128B apart)

// ---------------- cvt: W + U + Wout fp32->bf16, zero slots/rowsum ----------------
#define CVT_BLOCKS 2304
__global__ __launch_bounds__(256) void cvt_kernel(const float* __restrict__ W,
                                                  const float* __restrict__ U,
                                                  const float* __restrict__ Wout) {
    if (blockIdx.x == 0) {
        if (threadIdx.x < 64) g_slot[threadIdx.x * 32] = 0u;
        for (int i = threadIdx.x; i < Rn; i += 256) g_rowsum[i] = 0.0f;
    }
    const int nW    = Dh * Dh / 4;
    const int nU    = Dh * Dh / 4;
    const int nWout = Vn * Dh / 4;
    int i = blockIdx.x * 256 + threadIdx.x;
    const int stride = CVT_BLOCKS * 256;
    for (; i < nW + nU + nWout; i += stride) {
        float4 v;
        __nv_bfloat162* dst;
        if (i < nW) {
            v = ((const float4*)W)[i];
            dst = (__nv_bfloat162*)g_Wbf + 2 * (size_t)i;
        } else if (i < nW + nU) {
            int j = i - nW;
            v = ((const float4*)U)[j];
            dst = (__nv_bfloat162*)g_Ubf + 2 * (size_t)j;
        } else {
            int j = i - nW - nU;
            v = ((const float4*)Wout)[j];
            dst = (__nv_bfloat162*)g_Woutbf + 2 * (size_t)j;
        }
        dst[0] = __floats2bfloat162_rn(v.x, v.y);
        dst[1] = __floats2bfloat162_rn(v.z, v.w);
    }
}

// ---------------- embedding gather -> bf16 ----------------
__global__ __launch_bounds__(256) void embed_kernel(const int* __restrict__ idx,
                                                    const float* __restrict__ E) {
    int r = blockIdx.x;
    int id = idx[r];
    const float4* src = (const float4*)(E + (size_t)id * Dh);
    __nv_bfloat162* out = (__nv_bfloat162*)(g_xbf + (size_t)r * Dh);
    for (int i = threadIdx.x; i < Dh / 4; i += 256) {
        float4 v = src[i];
        out[2*i]   = __floats2bfloat162_rn(v.x, v.y);
        out[2*i+1] = __floats2bfloat162_rn(v.z, v.w);
    }
}

// ================= raw mma.sync bf16 NT GEMM: C[m,n] = sum_k A[m,k]*B[n,k] =================
#define BM 128
#define BN 128
#define BK 64
#define NST 3
#define AST (BM * BK * 2)
#define BST (BN * BK * 2)
#define GEMM_DSMEM (NST * (AST + BST))   // 96 KB

__device__ __forceinline__ uint32_t smem_u32(const void* p) {
    uint32_t a;
    asm("{ .reg .u64 t; cvta.to.shared.u64 t, %1; cvt.u32.u64 %0, t; }" : "=r"(a) : "l"(p));
    return a;
}
__device__ __forceinline__ void cp_async16(uint32_t dst, const void* src) {
    asm volatile("cp.async.cg.shared.global [%0], [%1], 16;" :: "r"(dst), "l"(src));
}
__device__ __forceinline__ void cp_commit() { asm volatile("cp.async.commit_group;"); }

__device__ __forceinline__ void ldsm4(uint32_t& r0, uint32_t& r1, uint32_t& r2, uint32_t& r3, uint32_t a) {
    asm volatile("ldmatrix.sync.aligned.m8n8.x4.shared.b16 {%0,%1,%2,%3}, [%4];"
                 : "=r"(r0), "=r"(r1), "=r"(r2), "=r"(r3) : "r"(a));
}
__device__ __forceinline__ void mma16816(float* d, const uint32_t* a, const uint32_t* b) {
    asm volatile("mma.sync.aligned.m16n8k16.row.col.f32.bf16.bf16.f32 "
                 "{%0,%1,%2,%3}, {%4,%5,%6,%7}, {%8,%9}, {%0,%1,%2,%3};"
                 : "+f"(d[0]), "+f"(d[1]), "+f"(d[2]), "+f"(d[3])
                 : "r"(a[0]), "r"(a[1]), "r"(a[2]), "r"(a[3]), "r"(b[0]), "r"(b[1]));
}

template <bool FUSE>
__global__ __launch_bounds__(256, 2) void gemm_mma(const __nv_bfloat16* __restrict__ A,
                                                   const __nv_bfloat16* __restrict__ Bm,
                                                   float* __restrict__ C,
                                                   int Nr, int Kr,
                                                   const float* __restrict__ bias,
                                                   float* __restrict__ rowsum) {
    extern __shared__ char smem[];
    const uint32_t sBase = smem_u32(smem);
    const uint32_t aS = sBase;
    const uint32_t bS = sBase + NST * AST;

    const int tid  = threadIdx.x;
    const int lane = tid & 31;
    const int wid  = tid >> 5;
    const int wm   = wid >> 2;
    const int wn   = wid & 3;
    const int bm = blockIdx.x, bn = blockIdx.y;
    const int KTILES = Kr / BK;

    uint32_t ld_phys[4];
    const __nv_bfloat16* aSrc[4];
    const __nv_bfloat16* bSrc[4];
    #pragma unroll
    for (int q = 0; q < 4; q++) {
        int task = q * 256 + tid;
        int row = task >> 3, ch = task & 7;
        uint32_t col = (uint32_t)ch * 16;
        ld_phys[q] = (uint32_t)row * 128 + (col ^ ((uint32_t)(row & 7) << 4));
        aSrc[q] = A  + (size_t)(bm * BM + row) * Kr + ch * 8;
        bSrc[q] = Bm + (size_t)(bn * BN + row) * Kr + ch * 8;
    }

    uint32_t aRowTerm[4], aPhase[4];
    const uint32_t aChunk = (uint32_t)(lane >> 4) * 16;
    #pragma unroll
    for (int i = 0; i < 4; i++) {
        int r = wm * 64 + i * 16 + (lane & 15);
        aRowTerm[i] = (uint32_t)r * 128;
        aPhase[i]   = (uint32_t)(r & 7) << 4;
    }
    uint32_t bRowTerm[2], bPhase[2];
    const uint32_t bChunk = (uint32_t)((lane >> 3) & 1) * 16;
    #pragma unroll
    for (int j = 0; j < 2; j++) {
        int n = wn * 32 + j * 16 + (lane & 7) + ((lane >> 4) << 3);
        bRowTerm[j] = (uint32_t)n * 128;
        bPhase[j]   = (uint32_t)(n & 7) << 4;
    }

    auto load_stage = [&](int st, int kt) {
        const int k0 = kt * BK;
        const uint32_t aOff = aS + st * AST;
        const uint32_t bOff = bS + st * BST;
        #pragma unroll
        for (int q = 0; q < 4; q++) {
            cp_async16(aOff + ld_phys[q], aSrc[q] + k0);
            cp_async16(bOff + ld_phys[q], bSrc[q] + k0);
        }
    };

    float acc[4][4][4];
    #pragma unroll
    for (int i = 0; i < 4; i++)
        #pragma unroll
        for (int j = 0; j < 4; j++)
            #pragma unroll
            for (int e = 0; e < 4; e++) acc[i][j][e] = 0.0f;

    load_stage(0, 0); cp_commit();
    load_stage(1, 1); cp_commit();

    for (int kt = 0; kt < KTILES; kt++) {
        const int st = kt % NST;
        asm volatile("cp.async.wait_group 1;" ::: "memory");
        __syncthreads();

        const int nf = kt + 2;
        if (nf < KTILES) load_stage(nf % NST, nf);
        cp_commit();

        const uint32_t aStage = aS + st * AST;
        const uint32_t bStage = bS + st * BST;
        #pragma unroll
        for (int s = 0; s < BK / 16; s++) {
            const uint32_t colA = (uint32_t)s * 32 + aChunk;
            const uint32_t colB = (uint32_t)s * 32 + bChunk;
            uint32_t a[4][4];
            #pragma unroll
            for (int i = 0; i < 4; i++)
                ldsm4(a[i][0], a[i][1], a[i][2], a[i][3],
                      aStage + aRowTerm[i] + (colA ^ aPhase[i]));
            uint32_t b[4][2];
            #pragma unroll
            for (int j = 0; j < 2; j++) {
                uint32_t r0, r1, r2, r3;
                ldsm4(r0, r1, r2, r3, bStage + bRowTerm[j] + (colB ^ bPhase[j]));
                b[2*j][0] = r0; b[2*j][1] = r1;
                b[2*j+1][0] = r2; b[2*j+1][1] = r3;
            }
            #pragma unroll
            for (int i = 0; i < 4; i++)
                #pragma unroll
                for (int j = 0; j < 4; j++)
                    mma16816(acc[i][j], a[i], b[j]);
        }
    }

    const int g = lane >> 2, tg = lane & 3;
    #pragma unroll
    for (int i = 0; i < 4; i++) {
        int row0 = bm * BM + wm * 64 + i * 16 + g;
        float p0 = 0.0f, p8 = 0.0f;
        #pragma unroll
        for (int j = 0; j < 4; j++) {
            int col = bn * BN + wn * 32 + j * 8 + tg * 2;
            float b0 = 0.0f, b1 = 0.0f;
            if (FUSE) { b0 = bias[col]; b1 = bias[col + 1]; }
            float v00 = acc[i][j][0] + b0, v01 = acc[i][j][1] + b1;
            float v10 = acc[i][j][2] + b0, v11 = acc[i][j][3] + b1;
            *(float2*)(C + (size_t)row0 * Nr + col)       = make_float2(v00, v01);
            *(float2*)(C + (size_t)(row0 + 8) * Nr + col) = make_float2(v10, v11);
            if (FUSE) {
                p0 += __expf(v00) + __expf(v01);
                p8 += __expf(v10) + __expf(v11);
            }
        }
        if (FUSE) {
            p0 += __shfl_xor_sync(0xffffffffu, p0, 1);
            p0 += __shfl_xor_sync(0xffffffffu, p0, 2);
            p8 += __shfl_xor_sync(0xffffffffu, p8, 1);
            p8 += __shfl_xor_sync(0xffffffffu, p8, 2);
            if (tg == 0) {
                atomicAdd(&rowsum[row0], p0);
                atomicAdd(&rowsum[row0 + 8], p8);
            }
        }
    }
}

// ====== persistent recurrence v8: tensor-core mma, full-K per block, 64 blocks ======
// Block bi owns 16 e's (E0 = bi*16). Warp w owns k-range [w*128, w*128+128).
// U slice held as bf16 mma B-fragments in registers. H_t broadcast via L2 (bf16).
__global__ __launch_bounds__(256) void rnn_kernel(const float* __restrict__ bWv,
                                                  const float* __restrict__ bUv) {
    const int tid  = threadIdx.x;
    const int w    = tid >> 5;
    const int lane = tid & 31;
    const int bi   = blockIdx.x;
    const int E0   = bi * 16;

    const int bn = lane >> 2;          // mma row/col group: batch row (A) / n (B)
    const int bk = (lane & 3) * 2;     // k pair within k16

    // B fragments: U[n = E0 + j*8 + bn][k = w*128 + s*16 + bk (+8)]
    uint32_t bf[2][8][2];
    #pragma unroll
    for (int j = 0; j < 2; j++)
        #pragma unroll
        for (int s = 0; s < 8; s++) {
            const __nv_bfloat16* up = g_Ubf + (size_t)(E0 + j * 8 + bn) * Dh + w * 128 + s * 16 + bk;
            bf[j][s][0] = *(const uint32_t*)up;
            bf[j][s][1] = *(const uint32_t*)(up + 8);
        }

    int bb = 0, el = 0;
    float bsum = 0.0f;
    if (tid < 128) {
        bb = tid >> 4; el = tid & 15;
        bsum = bWv[E0 + el] + bUv[E0 + el];
    }

    __shared__ float sp[8 * 128];   // per-warp partials [w][b*16+e_local]
    __shared__ float sh2[128];      // h floats [b][e_local]

    const uint32_t zero = 0u;

    for (int t = 0; t < Tn; t++) {
        float wx = 0.0f;
        if (tid < 128) wx = __ldcg(&g_Wx[(size_t)(bb * Tn + t) * Dh + E0 + el]);

        float c[2][4];
        #pragma unroll
        for (int j = 0; j < 2; j++)
            #pragma unroll
            for (int q = 0; q < 4; q++) c[j][q] = 0.0f;

        if (t > 0) {
            const __nv_bfloat16* Hp = g_hcur[(t - 1) & 1];
            #pragma unroll
            for (int s = 0; s < 8; s++) {
                const __nv_bfloat16* hp = Hp + (size_t)bn * Dh + w * 128 + s * 16 + bk;
                uint32_t aa[4];
                aa[0] = __ldcg((const uint32_t*)hp);
                aa[1] = zero;
                aa[2] = __ldcg((const uint32_t*)(hp + 8));
                aa[3] = zero;
                mma16816(c[0], aa, bf[0][s]);
                mma16816(c[1], aa, bf[1][s]);
            }
        }

        // write warp partials: c[j][0,1] = (b=bn, e_local = j*8 + bk, +1)
        #pragma unroll
        for (int j = 0; j < 2; j++)
            *(float2*)&sp[w * 128 + bn * 16 + j * 8 + bk] = make_float2(c[j][0], c[j][1]);
        __syncthreads();

        if (tid < 128) {
            float s2 = wx + bsum;
            #pragma unroll
            for (int w8 = 0; w8 < 8; w8++) s2 += sp[w8 * 128 + tid];
            sh2[tid] = tanhf(s2);
        }
        __syncthreads();

        if (tid < 64) {
            int b2 = tid >> 3, e2 = (tid & 7) * 2;
            __nv_bfloat162 hv = __floats2bfloat162_rn(sh2[b2 * 16 + e2], sh2[b2 * 16 + e2 + 1]);
            *(__nv_bfloat162*)&g_hcur[t & 1][b2 * Dh + E0 + e2] = hv;
            *(__nv_bfloat162*)&g_hbf[(size_t)(b2 * Tn + t) * Dh + E0 + e2] = hv;
        }
        __syncthreads();

        // ---- grid barrier: padded epoch slots, release store + 64-thread parallel poll ----
        if (tid == 0) {
            __threadfence();
            g_slot[bi * 32] = (unsigned)(t + 1);
        }
        for (;;) {
            bool ok = (tid < 64) ? (g_slot[tid * 32] >= (unsigned)(t + 1)) : true;
            if (__syncthreads_and(ok)) break;
        }
        __threadfence();
    }
}

// ---------------- final log_softmax subtract (single vectorized pass) ----------------
__global__ __launch_bounds__(256) void lse_final_kernel(float* __restrict__ C) {
    const int r = blockIdx.x;
    float4* row = (float4*)(C + (size_t)r * Vn);
    const float lse = __logf(g_rowsum[r]);
    for (int i = threadIdx.x; i < Vn / 4; i += 256) {
        float4 v = row[i];
        v.x -= lse; v.y -= lse; v.z -= lse; v.w -= lse;
        row[i] = v;
    }
}

// ---------------- launch ----------------
extern "C" void kernel_launch(void* const* d_in, const int* in_sizes, int n_in,
                              void* d_out, int out_size) {
    const int*   idx  = (const int*)d_in[0];
    const float* E    = (const float*)d_in[1];
    const float* W    = (const float*)d_in[2];
    const float* bW   = (const float*)d_in[3];
    const float* U    = (const float*)d_in[4];
    const float* bU   = (const float*)d_in[5];
    const float* Wout = (const float*)d_in[6];
    const float* bout = (const float*)d_in[7];
    float* out = (float*)d_out;

    void *p_xbf, *p_Wbf, *p_Woutbf, *p_Wx, *p_hbf, *p_rowsum;
    cudaGetSymbolAddress(&p_xbf,    g_xbf);
    cudaGetSymbolAddress(&p_Wbf,    g_Wbf);
    cudaGetSymbolAddress(&p_Woutbf, g_Woutbf);
    cudaGetSymbolAddress(&p_Wx,     g_Wx);
    cudaGetSymbolAddress(&p_hbf,    g_hbf);
    cudaGetSymbolAddress(&p_rowsum, g_rowsum);

    static int attr_set = 0;
    if (!attr_set) {
        cudaFuncSetAttribute(gemm_mma<false>, cudaFuncAttributeMaxDynamicSharedMemorySize, GEMM_DSMEM);
        cudaFuncSetAttribute(gemm_mma<true>,  cudaFuncAttributeMaxDynamicSharedMemorySize, GEMM_DSMEM);
        attr_set = 1;
    }

    // 1) cvt W/U/Wout + zero slots/rowsum
    cvt_kernel<<<CVT_BLOCKS, 256>>>(W, U, Wout);

    // 2) embedding gather
    embed_kernel<<<Rn, 256>>>(idx, E);

    // 3) input projection: Wx[r,e] = sum_d x[r,d] * W[e,d]
    gemm_mma<false><<<dim3(Rn / BM, Dh / BN), 256, GEMM_DSMEM>>>(
        (const __nv_bfloat16*)p_xbf, (const __nv_bfloat16*)p_Wbf, (float*)p_Wx,
        Dh, Dh, nullptr, nullptr);

    // 4) recurrence (tensor-core, 64 blocks)
    rnn_kernel<<<64, 256>>>(bW, bU);

    // 5) output projection with fused bias + exp-sum epilogue
    gemm_mma<true><<<dim3(Rn / BM, Vn / BN), 256, GEMM_DSMEM>>>(
        (const __nv_bfloat16*)p_hbf, (const __nv_bfloat16*)p_Woutbf, out,
        Vn, Dh, bout, (float*)p_rowsum);

    // 6) final: subtract log(sum exp) per row
    lse_final_kernel<<<Rn, 256>>>(out);
}